// round 3
// baseline (speedup 1.0000x reference)
#include <cuda_runtime.h>
#include <stdint.h>

#define KTAPS 27
#define CCH 64
#define TILE 16
#define THREADS 256

// ---------------- device-side self-configuration state ----------------
// cfg: [0]=mask_width(1/4/8) [1]=mask_slot(0..2) [2]=pin_slot(0..2)
//      [3]=pin_width(4/8)    [4]=pairslotA      [5]=pairslotB
__device__ int g_cfg[6];
// per-slot counters:
//  0 bad_u8   1 one_u8   2 bad_i32  3 one_i32  4 bad_f32  5 one_f32
//  6 bad_i64  7 one_i64  8 bad_f64  9 one_f64
// 10 io_bad_i32  11 io_bad_i64  12 arange_bad_i32  13 arange_bad_i64
__device__ unsigned long long g_cnt[3][16];

#define F32_ONE 0x3F800000u
#define F64_ONE 0x3FF0000000000000ULL

__global__ void kzero()
{
    int t = threadIdx.x;
    if (t < 48) g_cnt[t / 16][t % 16] = 0ull;
    if (t < 6)  g_cfg[t] = 0;
}

// Low-index probes: safe for ANY element width (max byte touched < 2 MB,
// every candidate array is >= 4.05 MB).
__global__ void kclassA(const void* c0, const void* c1, const void* c2, int N)
{
    const void* cand[3] = {c0, c1, c2};
    __shared__ unsigned long long sc[3][16];
    int t = threadIdx.x;
    if (t < 48) sc[t / 16][t % 16] = 0ull;
    __syncthreads();

    const int T = blockIdx.x * blockDim.x + threadIdx.x;
    const int STR = gridDim.x * blockDim.x;   // 24576

    for (int s = 0; s < 3; s++) {
        const uint8_t*  b8  = (const uint8_t*)cand[s];
        const unsigned* w32 = (const unsigned*)cand[s];
        const unsigned long long* q64 = (const unsigned long long*)cand[s];
        unsigned long long acc[14];
        #pragma unroll
        for (int i = 0; i < 14; i++) acc[i] = 0;

        for (int e = T; e < 480000; e += STR) {            // byte view
            uint8_t v = b8[e];
            acc[0] += (v > 1); acc[1] += (v == 1);
        }
        for (int e = T; e < 480000; e += STR) {            // 32-bit view
            unsigned w = w32[e];
            acc[2] += (w > 1); acc[3] += (w == 1);
            acc[4] += (w != 0u && w != F32_ONE); acc[5] += (w == F32_ONE);
            int k = e / N, n = e - k * N;
            acc[10] += (w != 0u && w != (unsigned)n);       // pair_out check
        }
        for (int e = T; e < 240000; e += STR) {            // 64-bit view
            unsigned long long q = q64[e];
            acc[6] += (q > 1ull); acc[7] += (q == 1ull);
            acc[8] += (q != 0ull && q != F64_ONE); acc[9] += (q == F64_ONE);
            int k = e / N, n = e - k * N;
            acc[11] += (q != 0ull && q != (unsigned long long)n);
        }
        #pragma unroll
        for (int i = 0; i < 14; i++)
            if (acc[i]) atomicAdd(&sc[s][i], acc[i]);
    }
    __syncthreads();
    if (t < 48) {
        unsigned long long v = sc[t / 16][t % 16];
        if (v) atomicAdd(&g_cnt[t / 16][t % 16], v);
    }
}

__global__ void kdecideA()
{
    // classify mask slot + width; remaining two slots are the pair arrays
    int mslot = -1, mwidth = 1;
    for (int s = 0; s < 3; s++) {
        const unsigned long long* c = g_cnt[s];
        int w = 0;
        if      (c[8] == 0 && c[9] > 0) w = 8;   // f64 mask
        else if (c[6] == 0 && c[7] > 0) w = 8;   // i64 mask
        else if (c[4] == 0 && c[5] > 0) w = 4;   // f32 mask
        else if (c[2] == 0 && c[3] > 0) w = 4;   // i32 mask
        else if (c[0] == 0 && c[1] > 0) w = 1;   // u8 mask
        if (w && mslot < 0) { mslot = s; mwidth = w; }
    }
    if (mslot < 0) { mslot = 2; mwidth = 1; }    // fallback: original layout
    g_cfg[0] = mwidth; g_cfg[1] = mslot;
    int pa = -1, pb = -1;
    for (int s = 0; s < 3; s++) if (s != mslot) { if (pa < 0) pa = s; else pb = s; }
    g_cfg[4] = pa; g_cfg[5] = pb;
}

// Self-tap arange probe on the two pair slots (both >= 16.2 MB, so an i64
// read at element 13N+1023 -> byte 15.6 MB is in bounds either way).
__global__ void kclassB(const void* c0, const void* c1, const void* c2, int N)
{
    const void* cand[3] = {c0, c1, c2};
    int t = threadIdx.x;
    for (int which = 0; which < 2; which++) {
        int s = g_cfg[4 + which];
        const int* w32 = (const int*)cand[s];
        const long long* q64 = (const long long*)cand[s];
        unsigned long long bad32 = 0, bad64 = 0;
        for (int p = t; p < 1024; p += blockDim.x) {
            long long base = 13LL * N + p;
            bad32 += (w32[base] != p);
            bad64 += (q64[base] != (long long)p);
        }
        if (bad32) atomicAdd(&g_cnt[s][12], bad32);
        if (bad64) atomicAdd(&g_cnt[s][13], bad64);
    }
}

__global__ void kdecideB()
{
    int pa = g_cfg[4], pb = g_cfg[5];
    int pw = (g_cnt[pa][12] == 0 && g_cnt[pb][12] == 0) ? 4 : 8;
    g_cfg[3] = pw;
    // pair_in has low-region values outside {0,n}; pair_out has none.
    int idx = (pw == 4) ? 10 : 11;
    unsigned long long va = g_cnt[pa][idx], vb = g_cnt[pb][idx];
    g_cfg[2] = (va >= vb) ? pa : pb;
}

// ---------------- main kernel ----------------
__global__ __launch_bounds__(THREADS)
void spdwconv_kernel(const float* __restrict__ features,
                     const float* __restrict__ weight,
                     const float* __restrict__ bias,
                     const void*  c0, const void* c1, const void* c2,
                     float* __restrict__ out,
                     int n)
{
    __shared__ int      pin_s[KTAPS][TILE];
    __shared__ unsigned bits_s[TILE];
    __shared__ float4   wsm[KTAPS * (CCH / 4)];

    const void* cand[3] = {c0, c1, c2};
    const int mw = g_cfg[0];
    const void* maskp = cand[g_cfg[1] & 3];
    const int   pw = g_cfg[3];
    const void* pinp = cand[g_cfg[2] & 3];

    const int t = threadIdx.x;
    const int n0 = blockIdx.x * TILE;

    if (t < TILE) bits_s[t] = 0u;
    __syncthreads();

    #pragma unroll
    for (int i = t; i < KTAPS * (CCH / 4); i += THREADS)
        wsm[i] = reinterpret_cast<const float4*>(weight)[i];

    for (int i = t; i < KTAPS * TILE; i += THREADS) {
        const int k = i / TILE;
        const int r = i - k * TILE;
        const int nn = n0 + r;
        if (nn < n) {
            const size_t off = (size_t)k * (size_t)n + (size_t)nn;
            bool m;
            if (mw == 1)      m = ((const uint8_t*)maskp)[off] != 0;
            else if (mw == 4) m = ((const unsigned*)maskp)[off] != 0u;
            else              m = ((const unsigned long long*)maskp)[off] != 0ull;
            int j = -1;
            if (m) {
                j = (pw == 4) ? ((const int*)pinp)[off]
                              : (int)((const long long*)pinp)[off];
                atomicOr(&bits_s[r], 1u << k);
            }
            pin_s[k][r] = j;
        }
    }
    __syncthreads();

    const int r  = t >> 4;
    const int c4 = t & 15;
    const int nn = n0 + r;
    if (nn >= n) return;

    float4 acc = reinterpret_cast<const float4*>(bias)[c4];
    unsigned b = bits_s[r];

    while (b) {
        const int k = __ffs(b) - 1;
        b &= b - 1;
        const int j = pin_s[k][r];
        const float4 fv = reinterpret_cast<const float4*>(features)[(size_t)j * 16 + c4];
        const float4 wv = wsm[k * 16 + c4];
        acc.x = fmaf(fv.x, wv.x, acc.x);
        acc.y = fmaf(fv.y, wv.y, acc.y);
        acc.z = fmaf(fv.z, wv.z, acc.z);
        acc.w = fmaf(fv.w, wv.w, acc.w);
    }

    reinterpret_cast<float4*>(out)[(size_t)nn * 16 + c4] = acc;
}

extern "C" void kernel_launch(void* const* d_in, const int* in_sizes, int n_in,
                              void* d_out, int out_size)
{
    // Map slots by element count (robust to ordering of same-size slots
    // being unknown: the three 27*N slots are disambiguated on-device).
    int fi = -1, wi = -1, bi = -1;
    int big[3], nbig = 0;
    long long maxc = -1;
    for (int i = 0; i < n_in; i++) if ((long long)in_sizes[i] > maxc) { maxc = in_sizes[i]; fi = i; }
    for (int i = 0; i < n_in; i++) {
        if (i == fi) continue;
        if (in_sizes[i] == 64) bi = i;
        else if (in_sizes[i] == KTAPS * CCH) wi = i;
        else if (nbig < 3) big[nbig++] = i;
    }
    const float* features = (const float*)d_in[fi];
    const float* weight   = (const float*)d_in[wi];
    const float* bias     = (const float*)d_in[bi];
    const void*  c0 = d_in[big[0]];
    const void*  c1 = d_in[big[1]];
    const void*  c2 = d_in[big[2]];
    float* out = (float*)d_out;

    const int n = in_sizes[fi] / CCH;

    kzero<<<1, 64>>>();
    kclassA<<<96, 256>>>(c0, c1, c2, n);
    kdecideA<<<1, 1>>>();
    kclassB<<<1, 256>>>(c0, c1, c2, n);
    kdecideB<<<1, 1>>>();

    const int grid = (n + TILE - 1) / TILE;
    spdwconv_kernel<<<grid, THREADS>>>(features, weight, bias, c0, c1, c2, out, n);
}

// round 4
// speedup vs baseline: 1.6041x; 1.6041x over previous
#include <cuda_runtime.h>
#include <stdint.h>

#define KTAPS 27
#define CCH 64
#define TILE 16
#define THREADS 256

// cfg: [0]=mask_kind (0 = 4-byte nonzero test, 1 = 2-byte/bf16 nonzero test)
//      [1]=mask_slot  [2]=pin_slot  [3]=pin_width (4 or 8)
__device__ int g_cfg[4];
// per-slot counters: 0 pairlike  1 one_i32  2 bf16_even_one  3 inout_bad
//                    4 arange_bad_i32
__device__ unsigned long long g_cnt[3][8];

#define F32_ONE   0x3F800000u
#define BF16_ONE  0x3F80

__global__ void kprobe(const void* c0, const void* c1, const void* c2, int N)
{
    const void* cand[3] = {c0, c1, c2};
    const int T   = blockIdx.x * blockDim.x + threadIdx.x;
    const int STR = gridDim.x * blockDim.x;
    if (T < 3 * 8) g_cnt[T / 8][T % 8] = 0ull;   // grid-wide race-free: every
    // block writes the same zeros before its own accumulation; atomics below
    // happen after each block's zeroing. To be safe, zero only from block 0 and
    // accumulate into shared first, merging once per block.
    __shared__ unsigned long long sc[3][8];
    if (threadIdx.x < 24) sc[threadIdx.x / 8][threadIdx.x % 8] = 0ull;
    __syncthreads();

    const int SAMPLE = 131072;   // all within tap 0 (N = 150000)
    for (int s = 0; s < 3; s++) {
        const unsigned*  w32 = (const unsigned*)cand[s];
        const uint16_t*  h16 = (const uint16_t*)cand[s];
        unsigned long long pairlike = 0, one32 = 0, evone = 0, iobad = 0;
        for (int e = T; e < SAMPLE; e += STR) {
            unsigned w = w32[e];
            bool maskpat = (w == 0u) || (w == 1u) || (w == F32_ONE) ||
                           (w == 0x3F803F80u) || (w == 0x00003F80u);
            pairlike += !maskpat;
            one32    += (w == 1u);
            iobad    += (w != 0u && w != (unsigned)e);    // tap0: pair_out==e
            uint16_t h = h16[2 * e];                      // even u16 index
            evone    += (h == BF16_ONE);
        }
        unsigned long long abad = 0;
        for (int p = T; p < 256; p += STR) {              // self-tap arange
            abad += (w32[13u * (unsigned)N + (unsigned)p] != (unsigned)p);
        }
        if (pairlike) atomicAdd(&sc[s][0], pairlike);
        if (one32)    atomicAdd(&sc[s][1], one32);
        if (evone)    atomicAdd(&sc[s][2], evone);
        if (iobad)    atomicAdd(&sc[s][3], iobad);
        if (abad)     atomicAdd(&sc[s][4], abad);
    }
    __syncthreads();
    if (threadIdx.x < 24) {
        unsigned long long v = sc[threadIdx.x / 8][threadIdx.x % 8];
        if (v) atomicAdd(&g_cnt[threadIdx.x / 8][threadIdx.x % 8], v);
    }
}

__global__ void kdecide()
{
    // mask slot: no pair-like words in sample
    int ms = -1;
    for (int s = 0; s < 3; s++)
        if (g_cnt[s][0] == 0 && ms < 0) ms = s;
    if (ms < 0) ms = 2;                          // fallback: metadata order
    // mask kind: i32 ones -> 4-byte test; bf16 even-index ones -> 2-byte test;
    // else f32 -> 4-byte test
    int mk = 0;
    if (g_cnt[ms][1] == 0 && g_cnt[ms][2] > 0) mk = 1;
    // pair slots
    int pa = -1, pb = -1;
    for (int s = 0; s < 3; s++) if (s != ms) { if (pa < 0) pa = s; else pb = s; }
    // pin width: both pair slots pass i32 self-tap arange -> 4
    int pw = (g_cnt[pa][4] == 0 && g_cnt[pb][4] == 0) ? 4 : 8;
    // pair_in = slot with values outside {0, n} in tap-0 sample
    int pin = (g_cnt[pa][3] >= g_cnt[pb][3]) ? pa : pb;
    g_cfg[0] = mk; g_cfg[1] = ms; g_cfg[2] = pin; g_cfg[3] = pw;
}

// ---------------- main kernel ----------------
__global__ __launch_bounds__(THREADS)
void spdwconv_kernel(const float* __restrict__ features,
                     const float* __restrict__ weight,   // [27*64], L1-resident
                     const float* __restrict__ bias,     // [64]
                     const void* c0, const void* c1, const void* c2,
                     float* __restrict__ out,
                     int n)
{
    __shared__ int      pin_s[KTAPS][TILE];
    __shared__ unsigned bits_s[TILE];

    const void* cand[3] = {c0, c1, c2};
    const int   mk    = g_cfg[0];
    const void* maskp = cand[g_cfg[1] & 3];
    const int   pw    = g_cfg[3];
    const void* pinp  = cand[g_cfg[2] & 3];

    const int t  = threadIdx.x;
    const int n0 = blockIdx.x * TILE;

    if (t < TILE) bits_s[t] = 0u;
    __syncthreads();

    // Stage per-row active taps + indices; predicated pair_in loads.
    for (int i = t; i < KTAPS * TILE; i += THREADS) {
        const int k  = i >> 4;           // TILE == 16
        const int r  = i & 15;
        const int nn = n0 + r;
        if (nn < n) {
            const size_t off = (size_t)k * (size_t)n + (size_t)nn;
            const bool m = (mk == 0) ? (((const unsigned*)maskp)[off] != 0u)
                                     : (((const uint16_t*)maskp)[off] != 0);
            int j = -1;
            if (m) {
                j = (pw == 4) ? ((const int*)pinp)[off]
                              : (int)((const long long*)pinp)[off];
                atomicOr(&bits_s[r], 1u << k);
            }
            pin_s[k][r] = j;
        }
    }
    __syncthreads();

    const int r  = t >> 4;        // row within tile
    const int c4 = t & 15;        // float4 channel group
    const int nn = n0 + r;
    if (nn >= n) return;

    float4 acc = reinterpret_cast<const float4*>(bias)[c4];
    unsigned b = bits_s[r];

    // Walk only active taps (avg ~1.4 of 27), ascending k (deterministic).
    while (b) {
        const int k = __ffs(b) - 1;
        b &= b - 1;
        const int j = pin_s[k][r];
        const float4 fv = reinterpret_cast<const float4*>(features)[(size_t)j * 16 + c4];
        const float4 wv = reinterpret_cast<const float4*>(weight)[k * 16 + c4];
        acc.x = fmaf(fv.x, wv.x, acc.x);
        acc.y = fmaf(fv.y, wv.y, acc.y);
        acc.z = fmaf(fv.z, wv.z, acc.z);
        acc.w = fmaf(fv.w, wv.w, acc.w);
    }

    reinterpret_cast<float4*>(out)[(size_t)nn * 16 + c4] = acc;
}

extern "C" void kernel_launch(void* const* d_in, const int* in_sizes, int n_in,
                              void* d_out, int out_size)
{
    int fi = -1, wi = -1, bi = -1;
    int big[3], nbig = 0;
    long long maxc = -1;
    for (int i = 0; i < n_in; i++)
        if ((long long)in_sizes[i] > maxc) { maxc = in_sizes[i]; fi = i; }
    for (int i = 0; i < n_in; i++) {
        if (i == fi) continue;
        if (in_sizes[i] == 64) bi = i;
        else if (in_sizes[i] == KTAPS * CCH) wi = i;
        else if (nbig < 3) big[nbig++] = i;
    }
    const float* features = (const float*)d_in[fi];
    const float* weight   = (const float*)d_in[wi];
    const float* bias     = (const float*)d_in[bi];
    const void*  c0 = d_in[big[0]];
    const void*  c1 = d_in[big[1]];
    const void*  c2 = d_in[big[2]];
    float* out = (float*)d_out;

    const int n = in_sizes[fi] / CCH;

    kprobe<<<48, 256>>>(c0, c1, c2, n);
    kdecide<<<1, 1>>>();

    const int grid = (n + TILE - 1) / TILE;
    spdwconv_kernel<<<grid, THREADS>>>(features, weight, bias, c0, c1, c2, out, n);
}

// round 5
// speedup vs baseline: 2.7962x; 1.7432x over previous
#include <cuda_runtime.h>
#include <stdint.h>

#define KTAPS 27
#define CCH 64
#define TILE 16
#define THREADS 256

// cfg: [0]=mask_kind (0 = 4-byte nonzero test, 1 = 2-byte/bf16 nonzero test)
//      [1]=mask_slot  [2]=pin_slot  [3]=pin_width (4 or 8)
__device__ int g_cfg[4];
// per-slot counters: 0 pairlike  1 one_i32  2 bf16_even_one  3 inout_bad
//                    4 arange_bad_i32
// Zero-initialized at load; kdecide re-zeroes AFTER deciding, so every graph
// replay starts from clean counters (no cross-block zeroing race).
__device__ unsigned long long g_cnt[3][8];

#define F32_ONE   0x3F800000u
#define BF16_ONE  0x3F80

#define PROBE_BLOCKS 96
#define PROBE_SAMPLE (PROBE_BLOCKS * 256)   // 24576, one element per thread

__global__ void kprobe(const void* c0, const void* c1, const void* c2, int N)
{
    const void* cand[3] = {c0, c1, c2};
    __shared__ unsigned long long sc[3][8];
    const int t = threadIdx.x;
    if (t < 24) sc[t / 8][t % 8] = 0ull;
    __syncthreads();

    const int e = blockIdx.x * blockDim.x + t;   // < PROBE_SAMPLE < N (tap 0)

    #pragma unroll
    for (int s = 0; s < 3; s++) {
        const unsigned* w32 = (const unsigned*)cand[s];
        const unsigned w = w32[e];
        const uint16_t h = (uint16_t)(w & 0xFFFFu);   // even u16 of this word

        const bool maskpat = (w == 0u) || (w == 1u) || (w == F32_ONE) ||
                             (w == 0x3F803F80u) || (w == 0x00003F80u);
        if (!maskpat)                    atomicAdd(&sc[s][0], 1ull);
        if (w == 1u)                     atomicAdd(&sc[s][1], 1ull);
        if (h == BF16_ONE)               atomicAdd(&sc[s][2], 1ull);
        if (w != 0u && w != (unsigned)e) atomicAdd(&sc[s][3], 1ull);   // tap0: out==e
        if (e < 256) {                   // self-tap arange check (i32 view)
            unsigned a = w32[13u * (unsigned)N + (unsigned)e];
            if (a != (unsigned)e)        atomicAdd(&sc[s][4], 1ull);
        }
    }
    __syncthreads();
    if (t < 24) {
        unsigned long long v = sc[t / 8][t % 8];
        if (v) atomicAdd(&g_cnt[t / 8][t % 8], v);
    }
}

__global__ void kdecide()
{
    // mask slot: no pair-like words in sample
    int ms = -1;
    for (int s = 0; s < 3; s++)
        if (g_cnt[s][0] == 0 && ms < 0) ms = s;
    if (ms < 0) ms = 2;                          // fallback: metadata order
    // mask kind: bf16 ones without i32 ones -> 2-byte test; else 4-byte test
    int mk = 0;
    if (g_cnt[ms][1] == 0 && g_cnt[ms][2] > 0) mk = 1;
    // pair slots
    int pa = -1, pb = -1;
    for (int s = 0; s < 3; s++) if (s != ms) { if (pa < 0) pa = s; else pb = s; }
    // pin width: both pair slots pass i32 self-tap arange -> 4
    int pw = (g_cnt[pa][4] == 0 && g_cnt[pb][4] == 0) ? 4 : 8;
    // pair_in = slot with values outside {0, n} in tap-0 sample
    int pin = (g_cnt[pa][3] >= g_cnt[pb][3]) ? pa : pb;
    g_cfg[0] = mk; g_cfg[1] = ms; g_cfg[2] = pin; g_cfg[3] = pw;

    // reset counters for the next replay of this graph
    for (int s = 0; s < 3; s++)
        for (int i = 0; i < 8; i++) g_cnt[s][i] = 0ull;
}

// ---------------- main kernel ----------------
__global__ __launch_bounds__(THREADS)
void spdwconv_kernel(const float* __restrict__ features,
                     const float* __restrict__ weight,   // [27*64], L1-resident
                     const float* __restrict__ bias,     // [64]
                     const void* c0, const void* c1, const void* c2,
                     float* __restrict__ out,
                     int n)
{
    __shared__ int      pin_s[KTAPS][TILE];
    __shared__ unsigned bits_s[TILE];

    const void* cand[3] = {c0, c1, c2};
    const int   mk    = g_cfg[0];
    const void* maskp = cand[g_cfg[1] & 3];
    const int   pw    = g_cfg[3];
    const void* pinp  = cand[g_cfg[2] & 3];

    const int t  = threadIdx.x;
    const int n0 = blockIdx.x * TILE;

    if (t < TILE) bits_s[t] = 0u;
    __syncthreads();

    // Stage per-row active taps + indices. Mask/pair are single-touch streams:
    // use streaming loads so they don't evict features from L2.
    for (int i = t; i < KTAPS * TILE; i += THREADS) {
        const int k  = i >> 4;           // TILE == 16
        const int r  = i & 15;
        const int nn = n0 + r;
        if (nn < n) {
            const size_t off = (size_t)k * (size_t)n + (size_t)nn;
            const bool m = (mk == 0)
                ? (__ldcs((const unsigned*)maskp + off) != 0u)
                : (__ldcs((const unsigned short*)maskp + off) != 0);
            int j = -1;
            if (m) {
                j = (pw == 4) ? __ldcs((const int*)pinp + off)
                              : (int)__ldcs((const long long*)pinp + off);
                atomicOr(&bits_s[r], 1u << k);
            }
            pin_s[k][r] = j;
        }
    }
    __syncthreads();

    const int r  = t >> 4;        // row within tile
    const int c4 = t & 15;        // float4 channel group
    const int nn = n0 + r;
    if (nn >= n) return;

    float4 acc = reinterpret_cast<const float4*>(bias)[c4];
    unsigned b = bits_s[r];

    // Walk only active taps (avg ~1.4 of 27), ascending k (deterministic).
    while (b) {
        const int k = __ffs(b) - 1;
        b &= b - 1;
        const int j = pin_s[k][r];
        const float4 fv = reinterpret_cast<const float4*>(features)[(size_t)j * 16 + c4];
        const float4 wv = reinterpret_cast<const float4*>(weight)[k * 16 + c4];
        acc.x = fmaf(fv.x, wv.x, acc.x);
        acc.y = fmaf(fv.y, wv.y, acc.y);
        acc.z = fmaf(fv.z, wv.z, acc.z);
        acc.w = fmaf(fv.w, wv.w, acc.w);
    }

    // Output is write-once: stream it past L2.
    __stcs(reinterpret_cast<float4*>(out) + (size_t)nn * 16 + c4, acc);
}

extern "C" void kernel_launch(void* const* d_in, const int* in_sizes, int n_in,
                              void* d_out, int out_size)
{
    int fi = -1, wi = -1, bi = -1;
    int big[3], nbig = 0;
    long long maxc = -1;
    for (int i = 0; i < n_in; i++)
        if ((long long)in_sizes[i] > maxc) { maxc = in_sizes[i]; fi = i; }
    for (int i = 0; i < n_in; i++) {
        if (i == fi) continue;
        if (in_sizes[i] == 64) bi = i;
        else if (in_sizes[i] == KTAPS * CCH) wi = i;
        else if (nbig < 3) big[nbig++] = i;
    }
    const float* features = (const float*)d_in[fi];
    const float* weight   = (const float*)d_in[wi];
    const float* bias     = (const float*)d_in[bi];
    const void*  c0 = d_in[big[0]];
    const void*  c1 = d_in[big[1]];
    const void*  c2 = d_in[big[2]];
    float* out = (float*)d_out;

    const int n = in_sizes[fi] / CCH;

    kprobe<<<PROBE_BLOCKS, 256>>>(c0, c1, c2, n);
    kdecide<<<1, 1>>>();

    const int grid = (n + TILE - 1) / TILE;
    spdwconv_kernel<<<grid, THREADS>>>(features, weight, bias, c0, c1, c2, out, n);
}

// round 6
// speedup vs baseline: 3.3463x; 1.1967x over previous
#include <cuda_runtime.h>
#include <stdint.h>

#define KTAPS 27
#define CCH 64
#define TILE 16
#define THREADS 256

// cfg: [0]=mask_kind (0 = 4-byte nonzero test, 1 = 2-byte/bf16 nonzero test)
//      [1]=mask_slot  [2]=pin_slot  [3]=pin_width (4 or 8)
__device__ int g_cfg[4];

#define F32_ONE   0x3F800000u
#define BF16_ONE  0x3F80

// ---------------- fused probe + decide (single block) ----------------
// Counters per slot: 0 pairlike  1 one_i32  2 bf16_even_one  3 inout_bad
//                    4 arange_bad_i32
__global__ void kprobe_decide(const void* c0, const void* c1, const void* c2, int N)
{
    const void* cand[3] = {c0, c1, c2};
    __shared__ unsigned sc[3][5];
    const int t = threadIdx.x;
    if (t < 15) ((unsigned*)sc)[t] = 0u;
    __syncthreads();

    unsigned acc[3][5];
    #pragma unroll
    for (int s = 0; s < 3; s++)
        #pragma unroll
        for (int i = 0; i < 5; i++) acc[s][i] = 0u;

    // 2048 samples per slot, all inside tap 0 (N >= 2048).
    #pragma unroll
    for (int it = 0; it < 8; it++) {
        const unsigned e = (unsigned)(it * 256 + t);
        #pragma unroll
        for (int s = 0; s < 3; s++) {
            const unsigned w = ((const unsigned*)cand[s])[e];
            const uint16_t h = (uint16_t)(w & 0xFFFFu);
            const bool maskpat = (w == 0u) || (w == 1u) || (w == F32_ONE) ||
                                 (w == 0x3F803F80u) || (w == 0x00003F80u);
            acc[s][0] += !maskpat;
            acc[s][1] += (w == 1u);
            acc[s][2] += (h == BF16_ONE);
            acc[s][3] += (w != 0u && w != e);      // tap0: pair_out == e
        }
    }
    // self-tap arange check (i32 view), elements 13*N + t
    #pragma unroll
    for (int s = 0; s < 3; s++) {
        const unsigned a = ((const unsigned*)cand[s])[13u * (unsigned)N + (unsigned)t];
        acc[s][4] += (a != (unsigned)t);
    }

    const int lane = t & 31;
    #pragma unroll
    for (int s = 0; s < 3; s++)
        #pragma unroll
        for (int i = 0; i < 5; i++) {
            unsigned v = __reduce_add_sync(0xFFFFFFFFu, acc[s][i]);
            if (lane == 0 && v) atomicAdd(&sc[s][i], v);
        }
    __syncthreads();

    if (t == 0) {
        int ms = -1;
        for (int s = 0; s < 3; s++)
            if (sc[s][0] == 0 && ms < 0) ms = s;
        if (ms < 0) ms = 2;
        int mk = (sc[ms][1] == 0 && sc[ms][2] > 0) ? 1 : 0;
        int pa = -1, pb = -1;
        for (int s = 0; s < 3; s++) if (s != ms) { if (pa < 0) pa = s; else pb = s; }
        int pw  = (sc[pa][4] == 0 && sc[pb][4] == 0) ? 4 : 8;
        int pin = (sc[pa][3] >= sc[pb][3]) ? pa : pb;
        g_cfg[0] = mk; g_cfg[1] = ms; g_cfg[2] = pin; g_cfg[3] = pw;
    }
}

// ---------------- main kernel ----------------
__global__ __launch_bounds__(THREADS)
void spdwconv_kernel(const float* __restrict__ features,
                     const float* __restrict__ weight,   // [27*64], L1-resident
                     const float* __restrict__ bias,     // [64]
                     const void* c0, const void* c1, const void* c2,
                     float* __restrict__ out,
                     int n)
{
    __shared__ int      pin_s[KTAPS][TILE];
    __shared__ unsigned bits_s[TILE];

    const void* cand[3] = {c0, c1, c2};
    const int   mk    = g_cfg[0];
    const void* maskp = cand[g_cfg[1] & 3];
    const int   pw    = g_cfg[3];
    const void* pinp  = cand[g_cfg[2] & 3];

    const int t  = threadIdx.x;
    const int n0 = blockIdx.x * TILE;

    if (t < TILE) bits_s[t] = 0u;
    __syncthreads();

    // Stage per-row active taps + indices. Mask/pair are single-touch streams.
    if (mk == 0 && (n & 3) == 0 && n0 + TILE <= n) {
        // Fast path: 4-byte mask, uint4 loads (16B-aligned since n%4==0 and
        // n0%16==0). 27 taps * 4 quads = 108 vector loads per block.
        for (int i = t; i < KTAPS * 4; i += THREADS) {
            const int k = i >> 2;
            const int q = i & 3;
            const size_t base = (size_t)k * (size_t)n + (size_t)(n0 + q * 4);
            const uint4 mv = __ldcs((const uint4*)((const unsigned*)maskp + base));
            const int r0 = q * 4;
            unsigned mbits = 0;
            int j0 = -1, j1 = -1, j2 = -1, j3 = -1;
            if (mv.x) { j0 = (pw == 4) ? __ldcs((const int*)pinp + base + 0)
                                       : (int)__ldcs((const long long*)pinp + base + 0); mbits |= 1u; }
            if (mv.y) { j1 = (pw == 4) ? __ldcs((const int*)pinp + base + 1)
                                       : (int)__ldcs((const long long*)pinp + base + 1); mbits |= 2u; }
            if (mv.z) { j2 = (pw == 4) ? __ldcs((const int*)pinp + base + 2)
                                       : (int)__ldcs((const long long*)pinp + base + 2); mbits |= 4u; }
            if (mv.w) { j3 = (pw == 4) ? __ldcs((const int*)pinp + base + 3)
                                       : (int)__ldcs((const long long*)pinp + base + 3); mbits |= 8u; }
            pin_s[k][r0 + 0] = j0;
            pin_s[k][r0 + 1] = j1;
            pin_s[k][r0 + 2] = j2;
            pin_s[k][r0 + 3] = j3;
            if (mbits & 1u) atomicOr(&bits_s[r0 + 0], 1u << k);
            if (mbits & 2u) atomicOr(&bits_s[r0 + 1], 1u << k);
            if (mbits & 4u) atomicOr(&bits_s[r0 + 2], 1u << k);
            if (mbits & 8u) atomicOr(&bits_s[r0 + 3], 1u << k);
        }
    } else {
        // Scalar fallback (2-byte mask / unaligned / tail block).
        for (int i = t; i < KTAPS * TILE; i += THREADS) {
            const int k  = i >> 4;
            const int r  = i & 15;
            const int nn = n0 + r;
            if (nn < n) {
                const size_t off = (size_t)k * (size_t)n + (size_t)nn;
                const bool m = (mk == 0)
                    ? (__ldcs((const unsigned*)maskp + off) != 0u)
                    : (__ldcs((const unsigned short*)maskp + off) != 0);
                int j = -1;
                if (m) {
                    j = (pw == 4) ? __ldcs((const int*)pinp + off)
                                  : (int)__ldcs((const long long*)pinp + off);
                    atomicOr(&bits_s[r], 1u << k);
                }
                pin_s[k][r] = j;
            }
        }
    }
    __syncthreads();

    const int r  = t >> 4;        // row within tile
    const int c4 = t & 15;        // float4 channel group
    const int nn = n0 + r;
    if (nn >= n) return;

    float4 acc = reinterpret_cast<const float4*>(bias)[c4];
    unsigned b = bits_s[r];

    // Walk only active taps (avg ~1.4 of 27), ascending k (deterministic).
    while (b) {
        const int k = __ffs(b) - 1;
        b &= b - 1;
        const int j = pin_s[k][r];
        const float4 fv = reinterpret_cast<const float4*>(features)[(size_t)j * 16 + c4];
        const float4 wv = reinterpret_cast<const float4*>(weight)[k * 16 + c4];
        acc.x = fmaf(fv.x, wv.x, acc.x);
        acc.y = fmaf(fv.y, wv.y, acc.y);
        acc.z = fmaf(fv.z, wv.z, acc.z);
        acc.w = fmaf(fv.w, wv.w, acc.w);
    }

    // Output is write-once: stream it past L2.
    __stcs(reinterpret_cast<float4*>(out) + (size_t)nn * 16 + c4, acc);
}

extern "C" void kernel_launch(void* const* d_in, const int* in_sizes, int n_in,
                              void* d_out, int out_size)
{
    int fi = -1, wi = -1, bi = -1;
    int big[3], nbig = 0;
    long long maxc = -1;
    for (int i = 0; i < n_in; i++)
        if ((long long)in_sizes[i] > maxc) { maxc = in_sizes[i]; fi = i; }
    for (int i = 0; i < n_in; i++) {
        if (i == fi) continue;
        if (in_sizes[i] == 64) bi = i;
        else if (in_sizes[i] == KTAPS * CCH) wi = i;
        else if (nbig < 3) big[nbig++] = i;
    }
    const float* features = (const float*)d_in[fi];
    const float* weight   = (const float*)d_in[wi];
    const float* bias     = (const float*)d_in[bi];
    const void*  c0 = d_in[big[0]];
    const void*  c1 = d_in[big[1]];
    const void*  c2 = d_in[big[2]];
    float* out = (float*)d_out;

    const int n = in_sizes[fi] / CCH;

    kprobe_decide<<<1, 256>>>(c0, c1, c2, n);

    const int grid = (n + TILE - 1) / TILE;
    spdwconv_kernel<<<grid, THREADS>>>(features, weight, bias, c0, c1, c2, out, n);
}